// round 2
// baseline (speedup 1.0000x reference)
#include <cuda_runtime.h>
#include <cstdint>
#include <math.h>

#define S_LEN 768
#define EMB   128
#define HDIM  256
#define G4    1024
#define MLPD  128

// ---------------- scratch (static device memory; no allocation) ----------------
__device__ float d_x  [S_LEN * EMB];
__device__ float d_gxF[S_LEN * G4];
__device__ float d_gxB[S_LEN * G4];
__device__ float d_h0 [S_LEN * 2 * HDIM];
__device__ float d_h1 [S_LEN * 2 * HDIM];
__device__ float d_hA [S_LEN * MLPD];
__device__ float d_hB [S_LEN * MLPD];

// ---------------- fast activations ----------------
__device__ __forceinline__ float sigmoidf_fast(float x) {
    return __fdividef(1.f, 1.f + __expf(-x));
}
__device__ __forceinline__ float tanhf_fast(float x) {
    float e = __expf(-2.f * fabsf(x));
    float r = __fdividef(1.f - e, 1.f + e);
    return copysignf(r, x);
}

// ---------------- cluster / mbarrier helpers ----------------
__device__ __forceinline__ uint32_t smem_u32(const void* p) {
    uint32_t a;
    asm("{ .reg .u64 t; cvta.to.shared.u64 t, %1; cvt.u32.u64 %0, t; }"
        : "=r"(a) : "l"(p));
    return a;
}
__device__ __forceinline__ uint32_t mapa_u32(uint32_t local_addr, uint32_t rank) {
    uint32_t rem;
    asm volatile("mapa.shared::cluster.u32 %0, %1, %2;"
                 : "=r"(rem) : "r"(local_addr), "r"(rank));
    return rem;
}
__device__ __forceinline__ void st_cluster_f32(uint32_t rem_addr, float v) {
    asm volatile("st.shared::cluster.f32 [%0], %1;" :: "r"(rem_addr), "f"(v) : "memory");
}
__device__ __forceinline__ void arrive_release_cluster(uint32_t rem_bar) {
    asm volatile("mbarrier.arrive.release.cluster.shared::cluster.b64 _, [%0];"
                 :: "r"(rem_bar) : "memory");
}
__device__ __forceinline__ void wait_parity_acq_cluster(uint32_t bar, uint32_t parity) {
    asm volatile(
        "{\n\t"
        ".reg .pred P;\n\t"
        "W%=:\n\t"
        "mbarrier.try_wait.parity.acquire.cluster.shared::cta.b64 P, [%0], %1;\n\t"
        "@!P bra W%=;\n\t"
        "}"
        :: "r"(bar), "r"(parity) : "memory");
}
__device__ __forceinline__ void cluster_sync_() {
    asm volatile("barrier.cluster.arrive.aligned;" ::: "memory");
    asm volatile("barrier.cluster.wait.aligned;" ::: "memory");
}
__device__ __forceinline__ uint32_t cluster_rank_() {
    uint32_t r; asm("mov.u32 %0, %%cluster_ctarank;" : "=r"(r)); return r;
}

#define FMA2(acc, w, h) \
    asm("fma.rn.f32x2 %0, %1, %2, %0;" : "+l"(acc) : "l"(w), "l"(h))

// ---------------- embedding gather ----------------
__global__ void embed_kernel(const int* __restrict__ widx, const int* __restrict__ pidx,
                             const float* __restrict__ Ww, const float* __restrict__ Wp) {
    int s = blockIdx.x, f = threadIdx.x;
    float v = (f < 100) ? Ww[widx[s] * 100 + f] : Wp[pidx[s] * 28 + (f - 100)];
    d_x[s * EMB + f] = v;
}

// ---------------- generic C[M,N] = A[M,K] * B[N,K]^T + bias1 + bias2 ----------------
__global__ __launch_bounds__(256) void gemm_bias_kernel(
    const float* __restrict__ A, int lda,
    const float* __restrict__ B, int ldb,
    const float* __restrict__ bias1, const float* __restrict__ bias2,
    float* __restrict__ C, int ldc,
    int M, int N, int K)
{
    __shared__ __align__(16) float As[16][68];
    __shared__ __align__(16) float Bs[16][68];
    int tid = threadIdx.x;
    int bx = blockIdx.x, by = blockIdx.y;
    int tx = tid & 15, ty = tid >> 4;
    int m0 = by * 64 + ty * 4;
    int n0 = bx * 64 + tx * 4;
    float acc[4][4] = {};

    for (int k0 = 0; k0 < K; k0 += 16) {
#pragma unroll
        for (int i = 0; i < 4; i++) {
            int idx = tid + i * 256;
            int r = idx >> 4, kk = idx & 15;
            int col = k0 + kk;
            int mrow = by * 64 + r;
            int nrow = bx * 64 + r;
            As[kk][r] = (mrow < M && col < K) ? A[mrow * lda + col] : 0.f;
            Bs[kk][r] = (nrow < N && col < K) ? B[nrow * ldb + col] : 0.f;
        }
        __syncthreads();
#pragma unroll
        for (int kk = 0; kk < 16; kk++) {
            float4 av = *reinterpret_cast<const float4*>(&As[kk][ty * 4]);
            float4 bv = *reinterpret_cast<const float4*>(&Bs[kk][tx * 4]);
            float a[4] = {av.x, av.y, av.z, av.w};
            float b[4] = {bv.x, bv.y, bv.z, bv.w};
#pragma unroll
            for (int i = 0; i < 4; i++)
#pragma unroll
                for (int j = 0; j < 4; j++)
                    acc[i][j] = fmaf(a[i], b[j], acc[i][j]);
        }
        __syncthreads();
    }
#pragma unroll
    for (int i = 0; i < 4; i++)
#pragma unroll
        for (int j = 0; j < 4; j++) {
            int r = m0 + i, c = n0 + j;
            if (r < M && c < N) {
                float bv = 0.f;
                if (bias1) bv += bias1[c];
                if (bias2) bv += bias2[c];
                C[r * ldc + c] = acc[i][j] + bv;
            }
        }
}

// ---------------- BiLSTM recurrence: 2 clusters x 8 CTAs x 256 threads ----------------
// Cluster 0 = forward dir, cluster 1 = backward dir.
// CTA owns 32 hidden units (128 gate rows). Thread (rl = tid>>1, hf = tid&1)
// holds 128 Whh weights (as 64 packed f32x2) for gate row `grow`, half `hf`.
// Sync per step: producer lanes st.shared::cluster the new h slice to each peer,
// then arrive (release, cluster) on that peer's ping-pong mbarrier. Consumers
// try_wait (acquire, cluster) on their local bar. No barrier.cluster in the loop.
__global__ void __cluster_dims__(8, 1, 1) __launch_bounds__(256, 1)
lstm_kernel(const float* __restrict__ WhhF, const float* __restrict__ WhhB,
            const float* __restrict__ gxF,  const float* __restrict__ gxB,
            float* __restrict__ hout)
{
    __shared__ __align__(16) float hbuf[2][264];   // [0,128) lower half, [132,260) upper half
    __shared__ float gates[128];
    __shared__ __align__(8) unsigned long long mbar[2];  // ping-pong (event parity)

    int tid   = threadIdx.x;
    uint32_t crank = cluster_rank_();
    int dir   = blockIdx.x >> 3;           // 0 = fwd, 1 = bwd
    const float* Whh = dir ? WhhB : WhhF;
    const float* gx  = dir ? gxB  : gxF;

    int rl   = tid >> 1;                   // local gate row 0..127
    int hf   = tid & 1;                    // which half of the 256 h values
    int gate = rl >> 5, unit = rl & 31;
    int grow = gate * 256 + (int)crank * 32 + unit;

    // register-resident weights, packed f32x2
    unsigned long long w2[64];
    const ulonglong2* wsrc = reinterpret_cast<const ulonglong2*>(Whh + grow * 256 + hf * 128);
#pragma unroll
    for (int k = 0; k < 32; k++) {
        ulonglong2 v = wsrc[k];
        w2[2 * k] = v.x; w2[2 * k + 1] = v.y;
    }

    for (int i = tid; i < 2 * 264; i += 256) (&hbuf[0][0])[i] = 0.f;
    if (tid == 0) {
        uint32_t b0 = smem_u32(&mbar[0]);
        asm volatile("mbarrier.init.shared.b64 [%0], 256;" :: "r"(b0) : "memory");
        asm volatile("mbarrier.init.shared.b64 [%0], 256;" :: "r"(b0 + 8) : "memory");
    }
    __syncthreads();
    cluster_sync_();   // all bars initialized + h zero before anyone stores/arrives

    float cstate = 0.f;
    uint32_t hbase   = smem_u32(&hbuf[0][0]);
    uint32_t barbase = smem_u32(&mbar[0]);

    // prefetch first gx
    int s0 = dir ? (S_LEN - 1) : 0;
    float gxv = gx[s0 * G4 + grow];

    for (int t = 0; t < S_LEN; t++) {
        int s = dir ? (S_LEN - 1 - t) : t;

        // wait for event t-1 (h(t) fully delivered) on bar[(t-1)&1]
        if (t > 0) {
            uint32_t e = (uint32_t)(t - 1);
            wait_parity_acq_cluster(barbase + (e & 1u) * 8u, (e >> 1) & 1u);
        }

        // prefetch next step's gx while we compute
        float gxn = 0.f;
        if (t + 1 < S_LEN) {
            int sn = dir ? (S_LEN - 2 - t) : (t + 1);
            gxn = gx[sn * G4 + grow];
        }

        // 128-wide dot product, packed f32x2
        const ulonglong2* hv = reinterpret_cast<const ulonglong2*>(&hbuf[t & 1][hf * 132]);
        unsigned long long acc0 = 0ull, acc1 = 0ull;  // (+0.f,+0.f)
#pragma unroll
        for (int k = 0; k < 32; k++) {
            ulonglong2 h2 = hv[k];
            FMA2(acc0, w2[2 * k],     h2.x);
            FMA2(acc1, w2[2 * k + 1], h2.y);
        }
        float a0, a1, a2, a3;
        asm("mov.b64 {%0, %1}, %2;" : "=f"(a0), "=f"(a1) : "l"(acc0));
        asm("mov.b64 {%0, %1}, %2;" : "=f"(a2), "=f"(a3) : "l"(acc1));
        float acc = (a0 + a1) + (a2 + a3);
        acc += __shfl_xor_sync(0xffffffffu, acc, 1);
        if (hf == 0) gates[rl] = gxv + acc;
        __syncthreads();

        if (tid < 32) {
            int u = tid;
            float gi = sigmoidf_fast(gates[u]);
            float gf = sigmoidf_fast(gates[32 + u]);
            float gg = tanhf_fast   (gates[64 + u]);
            float go = sigmoidf_fast(gates[96 + u]);
            cstate   = gf * cstate + gi * gg;
            float hn = go * tanhf_fast(cstate);

            int g = (int)crank * 32 + u;
            uint32_t off = (uint32_t)(((t + 1) & 1) * 264 + (g < 128 ? g : 132 + (g - 128))) * 4u;
            uint32_t hdst = hbase + off;
            uint32_t bdst = barbase + ((uint32_t)t & 1u) * 8u;   // event t -> bar[t&1]
#pragma unroll
            for (int p = 0; p < 8; p++) {
                uint32_t rh = mapa_u32(hdst, (uint32_t)p);
                uint32_t rb = mapa_u32(bdst, (uint32_t)p);
                st_cluster_f32(rh, hn);
                arrive_release_cluster(rb);   // same thread+path as the store: ordered
            }
            hout[s * 512 + dir * 256 + g] = hn;
        }
        gxv = gxn;
    }
    cluster_sync_();   // keep smem/bars alive until all in-flight remote ops land
}

// ---------------- pairwise scorer ----------------
__global__ __launch_bounds__(256) void scorer_kernel(
    const float* __restrict__ hA, const float* __restrict__ hB,
    const float* __restrict__ W2, const float* __restrict__ b2,
    float* __restrict__ out)
{
    __shared__ float sA[16][129];
    __shared__ float sB[16][129];
    __shared__ float sw[128];
    int tid = threadIdx.x;
    int j0 = blockIdx.x * 16, i0 = blockIdx.y * 16;

    for (int idx = tid; idx < 16 * 128; idx += 256) {
        int r = idx >> 7, k = idx & 127;
        sA[r][k] = hA[(i0 + r) * MLPD + k];
        sB[r][k] = hB[(j0 + r) * MLPD + k];
    }
    if (tid < 128) sw[tid] = W2[tid];
    __syncthreads();

    int tx = tid & 15, ty = tid >> 4;
    float acc = b2[0];
#pragma unroll 4
    for (int k = 0; k < 128; k++) {
        float v = sA[ty][k] + sB[tx][k];
        acc = fmaf(sw[k], tanhf_fast(v), acc);
    }
    int i = i0 + ty, j = j0 + tx;
    out[i * S_LEN + j] = (i == j) ? 0.f : acc;
}

// ---------------- launch ----------------
extern "C" void kernel_launch(void* const* d_in, const int* in_sizes, int n_in,
                              void* d_out, int out_size)
{
    int base = (in_sizes[2] < 1000) ? 3 : 2;

    const int* widx = (const int*)d_in[0];
    const int* pidx = (const int*)d_in[1];
    const float* W_word = (const float*)d_in[base + 0];
    const float* W_pos  = (const float*)d_in[base + 1];
    const float *Wih[4], *Whh[4], *bih[4], *bhh[4];
    for (int i = 0; i < 4; i++) {
        Wih[i] = (const float*)d_in[base + 2 + 4 * i];
        Whh[i] = (const float*)d_in[base + 3 + 4 * i];
        bih[i] = (const float*)d_in[base + 4 + 4 * i];
        bhh[i] = (const float*)d_in[base + 5 + 4 * i];
    }
    const float* W1 = (const float*)d_in[base + 18];
    const float* b1 = (const float*)d_in[base + 19];
    const float* W2 = (const float*)d_in[base + 20];
    const float* b2 = (const float*)d_in[base + 21];
    float* out = (float*)d_out;

    float *xp, *gxF, *gxB, *h0, *h1, *hA, *hB;
    cudaGetSymbolAddress((void**)&xp,  d_x);
    cudaGetSymbolAddress((void**)&gxF, d_gxF);
    cudaGetSymbolAddress((void**)&gxB, d_gxB);
    cudaGetSymbolAddress((void**)&h0,  d_h0);
    cudaGetSymbolAddress((void**)&h1,  d_h1);
    cudaGetSymbolAddress((void**)&hA,  d_hA);
    cudaGetSymbolAddress((void**)&hB,  d_hB);

    // 1) embeddings
    embed_kernel<<<S_LEN, EMB>>>(widx, pidx, W_word, W_pos);

    // 2) layer-0 input GEMMs: gx = x @ Wih^T + bih + bhh   [768,1024]
    dim3 gGX(G4 / 64, S_LEN / 64);
    gemm_bias_kernel<<<gGX, 256>>>(xp, EMB, Wih[0], EMB, bih[0], bhh[0], gxF, G4, S_LEN, G4, EMB);
    gemm_bias_kernel<<<gGX, 256>>>(xp, EMB, Wih[1], EMB, bih[1], bhh[1], gxB, G4, S_LEN, G4, EMB);

    // 3) layer-0 recurrence (fwd + bwd concurrently)
    lstm_kernel<<<16, 256>>>(Whh[0], Whh[1], gxF, gxB, h0);

    // 4) layer-1 input GEMMs: gx = h0 @ Wih^T + biases  (K = 512)
    gemm_bias_kernel<<<gGX, 256>>>(h0, 512, Wih[2], 512, bih[2], bhh[2], gxF, G4, S_LEN, G4, 512);
    gemm_bias_kernel<<<gGX, 256>>>(h0, 512, Wih[3], 512, bih[3], bhh[3], gxB, G4, S_LEN, G4, 512);

    // 5) layer-1 recurrence
    lstm_kernel<<<16, 256>>>(Whh[2], Whh[3], gxF, gxB, h1);

    // 6) scorer projections
    dim3 gAB(MLPD / 64, S_LEN / 64);
    gemm_bias_kernel<<<gAB, 256>>>(h1, 512, W1,       1024, b1,      nullptr, hA, MLPD, S_LEN, MLPD, 512);
    gemm_bias_kernel<<<gAB, 256>>>(h1, 512, W1 + 512, 1024, nullptr, nullptr, hB, MLPD, S_LEN, MLPD, 512);

    // 7) pairwise scores [768,768], diag = 0
    scorer_kernel<<<dim3(S_LEN / 16, S_LEN / 16), 256>>>(hA, hB, W2, b2, out);
}

// round 3
// speedup vs baseline: 1.6916x; 1.6916x over previous
#include <cuda_runtime.h>
#include <cstdint>
#include <math.h>

#define S_LEN 768
#define EMB   128
#define HDIM  256
#define G4    1024
#define MLPD  128

// ---------------- scratch (static device memory; no allocation) ----------------
__device__ float d_x  [S_LEN * EMB];
__device__ float d_gxF[S_LEN * G4];
__device__ float d_gxB[S_LEN * G4];
__device__ float d_h0 [S_LEN * 2 * HDIM];
__device__ float d_h1 [S_LEN * 2 * HDIM];
__device__ float d_hA [S_LEN * MLPD];
__device__ float d_hB [S_LEN * MLPD];

// ---------------- fast activations ----------------
__device__ __forceinline__ float sigmoidf_fast(float x) {
    return __fdividef(1.f, 1.f + __expf(-x));
}
__device__ __forceinline__ float tanhf_fast(float x) {
    float e = __expf(-2.f * fabsf(x));
    float r = __fdividef(1.f - e, 1.f + e);
    return copysignf(r, x);
}

// ---------------- cluster / mbarrier helpers ----------------
__device__ __forceinline__ uint32_t smem_u32(const void* p) {
    uint32_t a;
    asm("{ .reg .u64 t; cvta.to.shared.u64 t, %1; cvt.u32.u64 %0, t; }"
        : "=r"(a) : "l"(p));
    return a;
}
__device__ __forceinline__ uint32_t mapa_u32(uint32_t local_addr, uint32_t rank) {
    uint32_t rem;
    asm volatile("mapa.shared::cluster.u32 %0, %1, %2;"
                 : "=r"(rem) : "r"(local_addr), "r"(rank));
    return rem;
}
__device__ __forceinline__ void st_cluster_f32(uint32_t rem_addr, float v) {
    asm volatile("st.shared::cluster.f32 [%0], %1;" :: "r"(rem_addr), "f"(v) : "memory");
}
__device__ __forceinline__ void fence_acqrel_cluster() {
    asm volatile("fence.acq_rel.cluster;" ::: "memory");
}
__device__ __forceinline__ void arrive_release_cluster(uint32_t rem_bar) {
    asm volatile("mbarrier.arrive.release.cluster.shared::cluster.b64 _, [%0];"
                 :: "r"(rem_bar) : "memory");
}
// two-phase wait: fast try, then sleep-loop with timeout hint
__device__ __forceinline__ void wait_parity_acq_cluster(uint32_t bar, uint32_t parity) {
    uint32_t done;
    asm volatile(
        "{\n\t"
        ".reg .pred P;\n\t"
        "mbarrier.try_wait.parity.acquire.cluster.shared::cta.b64 P, [%1], %2;\n\t"
        "selp.b32 %0, 1, 0, P;\n\t"
        "}"
        : "=r"(done) : "r"(bar), "r"(parity) : "memory");
    if (!done) {
        asm volatile(
            "{\n\t"
            ".reg .pred P;\n\t"
            "W%=:\n\t"
            "mbarrier.try_wait.parity.acquire.cluster.shared::cta.b64 P, [%0], %1, 0x989680;\n\t"
            "@!P bra W%=;\n\t"
            "}"
            :: "r"(bar), "r"(parity) : "memory");
    }
}
__device__ __forceinline__ void cluster_sync_() {
    asm volatile("barrier.cluster.arrive.aligned;" ::: "memory");
    asm volatile("barrier.cluster.wait.aligned;" ::: "memory");
}
__device__ __forceinline__ uint32_t cluster_rank_() {
    uint32_t r; asm("mov.u32 %0, %%cluster_ctarank;" : "=r"(r)); return r;
}

#define FMA2(acc, w, h) \
    asm("fma.rn.f32x2 %0, %1, %2, %0;" : "+l"(acc) : "l"(w), "l"(h))

// ---------------- embedding gather ----------------
__global__ void embed_kernel(const int* __restrict__ widx, const int* __restrict__ pidx,
                             const float* __restrict__ Ww, const float* __restrict__ Wp) {
    int s = blockIdx.x, f = threadIdx.x;
    float v = (f < 100) ? Ww[widx[s] * 100 + f] : Wp[pidx[s] * 28 + (f - 100)];
    d_x[s * EMB + f] = v;
}

// ---------------- generic C[M,N] = A[M,K] * B[N,K]^T + bias1 + bias2 ----------------
__global__ __launch_bounds__(256) void gemm_bias_kernel(
    const float* __restrict__ A, int lda,
    const float* __restrict__ B, int ldb,
    const float* __restrict__ bias1, const float* __restrict__ bias2,
    float* __restrict__ C, int ldc,
    int M, int N, int K)
{
    __shared__ __align__(16) float As[16][68];
    __shared__ __align__(16) float Bs[16][68];
    int tid = threadIdx.x;
    int bx = blockIdx.x, by = blockIdx.y;
    int tx = tid & 15, ty = tid >> 4;
    int m0 = by * 64 + ty * 4;
    int n0 = bx * 64 + tx * 4;
    float acc[4][4] = {};

    for (int k0 = 0; k0 < K; k0 += 16) {
#pragma unroll
        for (int i = 0; i < 4; i++) {
            int idx = tid + i * 256;
            int r = idx >> 4, kk = idx & 15;
            int col = k0 + kk;
            int mrow = by * 64 + r;
            int nrow = bx * 64 + r;
            As[kk][r] = (mrow < M && col < K) ? A[mrow * lda + col] : 0.f;
            Bs[kk][r] = (nrow < N && col < K) ? B[nrow * ldb + col] : 0.f;
        }
        __syncthreads();
#pragma unroll
        for (int kk = 0; kk < 16; kk++) {
            float4 av = *reinterpret_cast<const float4*>(&As[kk][ty * 4]);
            float4 bv = *reinterpret_cast<const float4*>(&Bs[kk][tx * 4]);
            float a[4] = {av.x, av.y, av.z, av.w};
            float b[4] = {bv.x, bv.y, bv.z, bv.w};
#pragma unroll
            for (int i = 0; i < 4; i++)
#pragma unroll
                for (int j = 0; j < 4; j++)
                    acc[i][j] = fmaf(a[i], b[j], acc[i][j]);
        }
        __syncthreads();
    }
#pragma unroll
    for (int i = 0; i < 4; i++)
#pragma unroll
        for (int j = 0; j < 4; j++) {
            int r = m0 + i, c = n0 + j;
            if (r < M && c < N) {
                float bv = 0.f;
                if (bias1) bv += bias1[c];
                if (bias2) bv += bias2[c];
                C[r * ldc + c] = acc[i][j] + bv;
            }
        }
}

// ---------------- BiLSTM recurrence: 2 clusters x 8 CTAs x 256 threads ----------------
// Per step: producer lanes (tid<32) st.shared::cluster the new h slice to every
// peer, __syncwarp, ONE warp-wide fence.acq_rel.cluster (cumulative -> elevates
// all lanes' stores), then lanes 0..7 send ONE release-arrive each to one peer's
// ping-pong mbarrier (init count = 8). Consumers sleep-wait (acquire) on the
// local bar. No barrier.cluster and no arrival storm in the loop.
__global__ void __cluster_dims__(8, 1, 1) __launch_bounds__(256, 1)
lstm_kernel(const float* __restrict__ WhhF, const float* __restrict__ WhhB,
            const float* __restrict__ gxF,  const float* __restrict__ gxB,
            float* __restrict__ hout)
{
    __shared__ __align__(16) float hbuf[2][264];   // [0,128) lower half, [132,260) upper half
    __shared__ float gates[128];
    __shared__ __align__(8) unsigned long long mbar[2];  // ping-pong (bar[t&1])

    int tid   = threadIdx.x;
    uint32_t crank = cluster_rank_();
    int dir   = blockIdx.x >> 3;           // 0 = fwd, 1 = bwd
    const float* Whh = dir ? WhhB : WhhF;
    const float* gx  = dir ? gxB  : gxF;

    int rl   = tid >> 1;                   // local gate row 0..127
    int hf   = tid & 1;                    // which half of the 256 h values
    int gate = rl >> 5, unit = rl & 31;
    int grow = gate * 256 + (int)crank * 32 + unit;

    // register-resident weights, packed f32x2
    unsigned long long w2[64];
    const ulonglong2* wsrc = reinterpret_cast<const ulonglong2*>(Whh + grow * 256 + hf * 128);
#pragma unroll
    for (int k = 0; k < 32; k++) {
        ulonglong2 v = wsrc[k];
        w2[2 * k] = v.x; w2[2 * k + 1] = v.y;
    }

    for (int i = tid; i < 2 * 264; i += 256) (&hbuf[0][0])[i] = 0.f;
    if (tid == 0) {
        uint32_t b0 = smem_u32(&mbar[0]);
        asm volatile("mbarrier.init.shared.b64 [%0], 8;" :: "r"(b0) : "memory");
        asm volatile("mbarrier.init.shared.b64 [%0], 8;" :: "r"(b0 + 8) : "memory");
    }
    __syncthreads();
    cluster_sync_();   // all bars initialized + h zeroed before anyone stores/arrives

    float cstate = 0.f;
    uint32_t hbase   = smem_u32(&hbuf[0][0]);
    uint32_t barbase = smem_u32(&mbar[0]);

    // prefetch first gx
    int s0 = dir ? (S_LEN - 1) : 0;
    float gxv = gx[s0 * G4 + grow];

    for (int t = 0; t < S_LEN; t++) {
        int s = dir ? (S_LEN - 1 - t) : t;

        // wait for event t-1 (h(t) fully delivered) on bar[(t-1)&1]
        if (t > 0) {
            uint32_t e = (uint32_t)(t - 1);
            wait_parity_acq_cluster(barbase + (e & 1u) * 8u, (e >> 1) & 1u);
        }

        // prefetch next step's gx while we compute
        float gxn = 0.f;
        if (t + 1 < S_LEN) {
            int sn = dir ? (S_LEN - 2 - t) : (t + 1);
            gxn = gx[sn * G4 + grow];
        }

        // 128-wide dot product, packed f32x2
        const ulonglong2* hv = reinterpret_cast<const ulonglong2*>(&hbuf[t & 1][hf * 132]);
        unsigned long long acc0 = 0ull, acc1 = 0ull;  // (+0.f,+0.f)
#pragma unroll
        for (int k = 0; k < 32; k++) {
            ulonglong2 h2 = hv[k];
            FMA2(acc0, w2[2 * k],     h2.x);
            FMA2(acc1, w2[2 * k + 1], h2.y);
        }
        float a0, a1, a2, a3;
        asm("mov.b64 {%0, %1}, %2;" : "=f"(a0), "=f"(a1) : "l"(acc0));
        asm("mov.b64 {%0, %1}, %2;" : "=f"(a2), "=f"(a3) : "l"(acc1));
        float acc = (a0 + a1) + (a2 + a3);
        acc += __shfl_xor_sync(0xffffffffu, acc, 1);
        if (hf == 0) gates[rl] = gxv + acc;
        __syncthreads();

        if (tid < 32) {
            int u = tid;
            float gi = sigmoidf_fast(gates[u]);
            float gf = sigmoidf_fast(gates[32 + u]);
            float gg = tanhf_fast   (gates[64 + u]);
            float go = sigmoidf_fast(gates[96 + u]);
            cstate   = gf * cstate + gi * gg;
            float hn = go * tanhf_fast(cstate);

            int g = (int)crank * 32 + u;
            uint32_t off = (uint32_t)(((t + 1) & 1) * 264 + (g < 128 ? g : 132 + (g - 128))) * 4u;
            uint32_t hdst = hbase + off;
#pragma unroll
            for (int p = 0; p < 8; p++)
                st_cluster_f32(mapa_u32(hdst, (uint32_t)p), hn);
            __syncwarp();
            fence_acqrel_cluster();               // elevate all lanes' stores to cluster scope
            if (u < 8) {
                uint32_t bdst = barbase + ((uint32_t)t & 1u) * 8u;   // event t -> bar[t&1]
                arrive_release_cluster(mapa_u32(bdst, (uint32_t)u)); // 1 arrival per peer
            }
            hout[s * 512 + dir * 256 + g] = hn;
        }
        gxv = gxn;
    }
    cluster_sync_();   // keep smem/bars alive until all in-flight remote ops land
}

// ---------------- pairwise scorer ----------------
__global__ __launch_bounds__(256) void scorer_kernel(
    const float* __restrict__ hA, const float* __restrict__ hB,
    const float* __restrict__ W2, const float* __restrict__ b2,
    float* __restrict__ out)
{
    __shared__ float sA[16][129];
    __shared__ float sB[16][129];
    __shared__ float sw[128];
    int tid = threadIdx.x;
    int j0 = blockIdx.x * 16, i0 = blockIdx.y * 16;

    for (int idx = tid; idx < 16 * 128; idx += 256) {
        int r = idx >> 7, k = idx & 127;
        sA[r][k] = hA[(i0 + r) * MLPD + k];
        sB[r][k] = hB[(j0 + r) * MLPD + k];
    }
    if (tid < 128) sw[tid] = W2[tid];
    __syncthreads();

    int tx = tid & 15, ty = tid >> 4;
    float acc = b2[0];
#pragma unroll 4
    for (int k = 0; k < 128; k++) {
        float v = sA[ty][k] + sB[tx][k];
        acc = fmaf(sw[k], tanhf_fast(v), acc);
    }
    int i = i0 + ty, j = j0 + tx;
    out[i * S_LEN + j] = (i == j) ? 0.f : acc;
}

// ---------------- launch ----------------
extern "C" void kernel_launch(void* const* d_in, const int* in_sizes, int n_in,
                              void* d_out, int out_size)
{
    int base = (in_sizes[2] < 1000) ? 3 : 2;

    const int* widx = (const int*)d_in[0];
    const int* pidx = (const int*)d_in[1];
    const float* W_word = (const float*)d_in[base + 0];
    const float* W_pos  = (const float*)d_in[base + 1];
    const float *Wih[4], *Whh[4], *bih[4], *bhh[4];
    for (int i = 0; i < 4; i++) {
        Wih[i] = (const float*)d_in[base + 2 + 4 * i];
        Whh[i] = (const float*)d_in[base + 3 + 4 * i];
        bih[i] = (const float*)d_in[base + 4 + 4 * i];
        bhh[i] = (const float*)d_in[base + 5 + 4 * i];
    }
    const float* W1 = (const float*)d_in[base + 18];
    const float* b1 = (const float*)d_in[base + 19];
    const float* W2 = (const float*)d_in[base + 20];
    const float* b2 = (const float*)d_in[base + 21];
    float* out = (float*)d_out;

    float *xp, *gxF, *gxB, *h0, *h1, *hA, *hB;
    cudaGetSymbolAddress((void**)&xp,  d_x);
    cudaGetSymbolAddress((void**)&gxF, d_gxF);
    cudaGetSymbolAddress((void**)&gxB, d_gxB);
    cudaGetSymbolAddress((void**)&h0,  d_h0);
    cudaGetSymbolAddress((void**)&h1,  d_h1);
    cudaGetSymbolAddress((void**)&hA,  d_hA);
    cudaGetSymbolAddress((void**)&hB,  d_hB);

    // 1) embeddings
    embed_kernel<<<S_LEN, EMB>>>(widx, pidx, W_word, W_pos);

    // 2) layer-0 input GEMMs: gx = x @ Wih^T + bih + bhh   [768,1024]
    dim3 gGX(G4 / 64, S_LEN / 64);
    gemm_bias_kernel<<<gGX, 256>>>(xp, EMB, Wih[0], EMB, bih[0], bhh[0], gxF, G4, S_LEN, G4, EMB);
    gemm_bias_kernel<<<gGX, 256>>>(xp, EMB, Wih[1], EMB, bih[1], bhh[1], gxB, G4, S_LEN, G4, EMB);

    // 3) layer-0 recurrence (fwd + bwd concurrently)
    lstm_kernel<<<16, 256>>>(Whh[0], Whh[1], gxF, gxB, h0);

    // 4) layer-1 input GEMMs: gx = h0 @ Wih^T + biases  (K = 512)
    gemm_bias_kernel<<<gGX, 256>>>(h0, 512, Wih[2], 512, bih[2], bhh[2], gxF, G4, S_LEN, G4, 512);
    gemm_bias_kernel<<<gGX, 256>>>(h0, 512, Wih[3], 512, bih[3], bhh[3], gxB, G4, S_LEN, G4, 512);

    // 5) layer-1 recurrence
    lstm_kernel<<<16, 256>>>(Whh[2], Whh[3], gxF, gxB, h1);

    // 6) scorer projections
    dim3 gAB(MLPD / 64, S_LEN / 64);
    gemm_bias_kernel<<<gAB, 256>>>(h1, 512, W1,       1024, b1,      nullptr, hA, MLPD, S_LEN, MLPD, 512);
    gemm_bias_kernel<<<gAB, 256>>>(h1, 512, W1 + 512, 1024, nullptr, nullptr, hB, MLPD, S_LEN, MLPD, 512);

    // 7) pairwise scores [768,768], diag = 0
    scorer_kernel<<<dim3(S_LEN / 16, S_LEN / 16), 256>>>(hA, hB, W2, b2, out);
}

// round 4
// speedup vs baseline: 2.1405x; 1.2654x over previous
#include <cuda_runtime.h>
#include <cstdint>
#include <math.h>

#define S_LEN 768
#define EMB   128
#define HDIM  256
#define G4    1024
#define MLPD  128

// ---------------- scratch (static device memory; no allocation) ----------------
__device__ float d_x  [S_LEN * EMB];
__device__ float d_gxF[S_LEN * G4];
__device__ float d_gxB[S_LEN * G4];
__device__ float d_h0 [S_LEN * 2 * HDIM];
__device__ float d_h1 [S_LEN * 2 * HDIM];
__device__ float d_hA [S_LEN * MLPD];
__device__ float d_hB [S_LEN * MLPD];

// ---------------- fast activations ----------------
__device__ __forceinline__ float sigmoidf_fast(float x) {
    return __fdividef(1.f, 1.f + __expf(-x));
}
__device__ __forceinline__ float tanhf_fast(float x) {
    float e = __expf(-2.f * fabsf(x));
    float r = __fdividef(1.f - e, 1.f + e);
    return copysignf(r, x);
}

// ---------------- cluster / mbarrier helpers ----------------
__device__ __forceinline__ uint32_t smem_u32(const void* p) {
    uint32_t a;
    asm("{ .reg .u64 t; cvta.to.shared.u64 t, %1; cvt.u32.u64 %0, t; }"
        : "=r"(a) : "l"(p));
    return a;
}
__device__ __forceinline__ uint32_t mapa_u32(uint32_t local_addr, uint32_t rank) {
    uint32_t rem;
    asm volatile("mapa.shared::cluster.u32 %0, %1, %2;"
                 : "=r"(rem) : "r"(local_addr), "r"(rank));
    return rem;
}
// bulk DSMEM copy with tx-completion at the (remote) destination mbarrier
__device__ __forceinline__ void bulk_copy_cluster(uint32_t dst_cluster, uint32_t src_cta,
                                                  uint32_t bytes, uint32_t bar_cluster) {
    asm volatile(
        "cp.async.bulk.shared::cluster.shared::cta.mbarrier::complete_tx::bytes "
        "[%0], [%1], %2, [%3];"
        :: "r"(dst_cluster), "r"(src_cta), "r"(bytes), "r"(bar_cluster) : "memory");
}
__device__ __forceinline__ void fence_proxy_async_cta() {
    asm volatile("fence.proxy.async.shared::cta;" ::: "memory");
}
__device__ __forceinline__ void arrive_expect_tx(uint32_t bar, uint32_t bytes) {
    asm volatile("mbarrier.arrive.expect_tx.shared.b64 _, [%0], %1;"
                 :: "r"(bar), "r"(bytes) : "memory");
}
// two-phase wait: fast try, then sleep-loop with timeout hint
__device__ __forceinline__ void wait_parity(uint32_t bar, uint32_t parity) {
    uint32_t done;
    asm volatile(
        "{\n\t"
        ".reg .pred P;\n\t"
        "mbarrier.try_wait.parity.acquire.cta.shared::cta.b64 P, [%1], %2;\n\t"
        "selp.b32 %0, 1, 0, P;\n\t"
        "}"
        : "=r"(done) : "r"(bar), "r"(parity) : "memory");
    if (!done) {
        asm volatile(
            "{\n\t"
            ".reg .pred P;\n\t"
            "W%=:\n\t"
            "mbarrier.try_wait.parity.acquire.cta.shared::cta.b64 P, [%0], %1, 0x989680;\n\t"
            "@!P bra W%=;\n\t"
            "}"
            :: "r"(bar), "r"(parity) : "memory");
    }
}
__device__ __forceinline__ void cluster_sync_() {
    asm volatile("barrier.cluster.arrive.aligned;" ::: "memory");
    asm volatile("barrier.cluster.wait.aligned;" ::: "memory");
}
__device__ __forceinline__ uint32_t cluster_rank_() {
    uint32_t r; asm("mov.u32 %0, %%cluster_ctarank;" : "=r"(r)); return r;
}

#define FMA2(acc, w, h) \
    asm("fma.rn.f32x2 %0, %1, %2, %0;" : "+l"(acc) : "l"(w), "l"(h))

// ---------------- embedding gather ----------------
__global__ void embed_kernel(const int* __restrict__ widx, const int* __restrict__ pidx,
                             const float* __restrict__ Ww, const float* __restrict__ Wp) {
    int s = blockIdx.x, f = threadIdx.x;
    float v = (f < 100) ? Ww[widx[s] * 100 + f] : Wp[pidx[s] * 28 + (f - 100)];
    d_x[s * EMB + f] = v;
}

// ---------------- generic C[M,N] = A[M,K] * B[N,K]^T + bias1 + bias2 ----------------
__global__ __launch_bounds__(256) void gemm_bias_kernel(
    const float* __restrict__ A, int lda,
    const float* __restrict__ B, int ldb,
    const float* __restrict__ bias1, const float* __restrict__ bias2,
    float* __restrict__ C, int ldc,
    int M, int N, int K)
{
    __shared__ __align__(16) float As[16][68];
    __shared__ __align__(16) float Bs[16][68];
    int tid = threadIdx.x;
    int bx = blockIdx.x, by = blockIdx.y;
    int tx = tid & 15, ty = tid >> 4;
    int m0 = by * 64 + ty * 4;
    int n0 = bx * 64 + tx * 4;
    float acc[4][4] = {};

    for (int k0 = 0; k0 < K; k0 += 16) {
#pragma unroll
        for (int i = 0; i < 4; i++) {
            int idx = tid + i * 256;
            int r = idx >> 4, kk = idx & 15;
            int col = k0 + kk;
            int mrow = by * 64 + r;
            int nrow = bx * 64 + r;
            As[kk][r] = (mrow < M && col < K) ? A[mrow * lda + col] : 0.f;
            Bs[kk][r] = (nrow < N && col < K) ? B[nrow * ldb + col] : 0.f;
        }
        __syncthreads();
#pragma unroll
        for (int kk = 0; kk < 16; kk++) {
            float4 av = *reinterpret_cast<const float4*>(&As[kk][ty * 4]);
            float4 bv = *reinterpret_cast<const float4*>(&Bs[kk][tx * 4]);
            float a[4] = {av.x, av.y, av.z, av.w};
            float b[4] = {bv.x, bv.y, bv.z, bv.w};
#pragma unroll
            for (int i = 0; i < 4; i++)
#pragma unroll
                for (int j = 0; j < 4; j++)
                    acc[i][j] = fmaf(a[i], b[j], acc[i][j]);
        }
        __syncthreads();
    }
#pragma unroll
    for (int i = 0; i < 4; i++)
#pragma unroll
        for (int j = 0; j < 4; j++) {
            int r = m0 + i, c = n0 + j;
            if (r < M && c < N) {
                float bv = 0.f;
                if (bias1) bv += bias1[c];
                if (bias2) bv += bias2[c];
                C[r * ldc + c] = acc[i][j] + bv;
            }
        }
}

// ---------------- BiLSTM recurrence: 2 clusters x 8 CTAs x 256 threads ----------------
// Cross-CTA h exchange via async-proxy bulk copies (no cluster-scope fence, no
// L1D flush, no arrival storm):
//   - warp 0 writes its 32 new h values to a 128B staging buffer (STS)
//   - fence.proxy.async.shared::cta (generic -> async proxy, CTA scope)
//   - lanes 0..7 each issue ONE cp.async.bulk (128B) to one peer's hbuf slot,
//     with mbarrier::complete_tx at that peer's ping-pong bar
//   - each CTA re-arms its local bar with arrive.expect_tx(1024) (count=1);
//     tx-count may go negative if deliveries race the arm - that is legal
//   - waiters use try_wait.parity with sleep hint
__global__ void __cluster_dims__(8, 1, 1) __launch_bounds__(256, 1)
lstm_kernel(const float* __restrict__ WhhF, const float* __restrict__ WhhB,
            const float* __restrict__ gxF,  const float* __restrict__ gxB,
            float* __restrict__ hout)
{
    __shared__ __align__(16) float hbuf[2][256];   // ping-pong full h vector
    __shared__ __align__(16) float stage[32];      // 128B outgoing slice
    __shared__ float gates[128];
    __shared__ __align__(8) unsigned long long mbar[2];  // ping-pong (bar[t&1])

    int tid   = threadIdx.x;
    uint32_t crank = cluster_rank_();
    int dir   = blockIdx.x >> 3;           // 0 = fwd, 1 = bwd
    const float* Whh = dir ? WhhB : WhhF;
    const float* gx  = dir ? gxB  : gxF;

    int rl   = tid >> 1;                   // local gate row 0..127
    int hf   = tid & 1;                    // which half of the 256 h values
    int gate = rl >> 5, unit = rl & 31;
    int grow = gate * 256 + (int)crank * 32 + unit;

    // register-resident weights, packed f32x2
    unsigned long long w2[64];
    const ulonglong2* wsrc = reinterpret_cast<const ulonglong2*>(Whh + grow * 256 + hf * 128);
#pragma unroll
    for (int k = 0; k < 32; k++) {
        ulonglong2 v = wsrc[k];
        w2[2 * k] = v.x; w2[2 * k + 1] = v.y;
    }

    for (int i = tid; i < 512; i += 256) (&hbuf[0][0])[i] = 0.f;
    if (tid == 0) {
        uint32_t b0 = smem_u32(&mbar[0]);
        asm volatile("mbarrier.init.shared.b64 [%0], 1;" :: "r"(b0) : "memory");
        asm volatile("mbarrier.init.shared.b64 [%0], 1;" :: "r"(b0 + 8) : "memory");
    }
    __syncthreads();
    cluster_sync_();   // bars initialized + h zeroed before anyone copies/arrives

    float cstate = 0.f;
    uint32_t hbase   = smem_u32(&hbuf[0][0]);
    uint32_t stbase  = smem_u32(&stage[0]);
    uint32_t barbase = smem_u32(&mbar[0]);

    // prefetch first gx
    int s0 = dir ? (S_LEN - 1) : 0;
    float gxv = gx[s0 * G4 + grow];

    for (int t = 0; t < S_LEN; t++) {
        int s = dir ? (S_LEN - 1 - t) : t;

        // re-arm local bar for event t (this step's incoming deliveries).
        // Safe: bar[t&1]'s previous event (t-2) completed before our step t-1 wait.
        if (tid == 0)
            arrive_expect_tx(barbase + ((uint32_t)t & 1u) * 8u, 1024u);

        // wait for event t-1 (h(t) fully delivered into hbuf[t&1])
        if (t > 0) {
            uint32_t e = (uint32_t)(t - 1);
            wait_parity(barbase + (e & 1u) * 8u, (e >> 1) & 1u);
        }

        // prefetch next step's gx while we compute
        float gxn = 0.f;
        if (t + 1 < S_LEN) {
            int sn = dir ? (S_LEN - 2 - t) : (t + 1);
            gxn = gx[sn * G4 + grow];
        }

        // 128-wide dot product, packed f32x2
        const ulonglong2* hv = reinterpret_cast<const ulonglong2*>(&hbuf[t & 1][hf * 128]);
        unsigned long long acc0 = 0ull, acc1 = 0ull;  // (+0.f,+0.f)
#pragma unroll
        for (int k = 0; k < 32; k++) {
            ulonglong2 h2 = hv[k];
            FMA2(acc0, w2[2 * k],     h2.x);
            FMA2(acc1, w2[2 * k + 1], h2.y);
        }
        float a0, a1, a2, a3;
        asm("mov.b64 {%0, %1}, %2;" : "=f"(a0), "=f"(a1) : "l"(acc0));
        asm("mov.b64 {%0, %1}, %2;" : "=f"(a2), "=f"(a3) : "l"(acc1));
        float acc = (a0 + a1) + (a2 + a3);
        acc += __shfl_xor_sync(0xffffffffu, acc, 1);
        if (hf == 0) gates[rl] = gxv + acc;
        __syncthreads();

        if (tid < 32) {
            int u = tid;
            float gi = sigmoidf_fast(gates[u]);
            float gf = sigmoidf_fast(gates[32 + u]);
            float gg = tanhf_fast   (gates[64 + u]);
            float go = sigmoidf_fast(gates[96 + u]);
            cstate   = gf * cstate + gi * gg;
            float hn = go * tanhf_fast(cstate);

            stage[u] = hn;
            int g = (int)crank * 32 + u;
            hout[s * 512 + dir * 256 + g] = hn;
            __syncwarp();
            fence_proxy_async_cta();   // make stage visible to the async proxy
            if (u < 8) {
                uint32_t hoff = (uint32_t)(((t + 1) & 1) * 256 + (int)crank * 32) * 4u;
                uint32_t dst  = mapa_u32(hbase + hoff, (uint32_t)u);
                uint32_t rb   = mapa_u32(barbase + ((uint32_t)t & 1u) * 8u, (uint32_t)u);
                bulk_copy_cluster(dst, stbase, 128u, rb);   // 128B slice + tx at peer bar
            }
        }
        gxv = gxn;
    }
    cluster_sync_();   // keep smem/bars alive until all in-flight remote ops land
}

// ---------------- pairwise scorer ----------------
__global__ __launch_bounds__(256) void scorer_kernel(
    const float* __restrict__ hA, const float* __restrict__ hB,
    const float* __restrict__ W2, const float* __restrict__ b2,
    float* __restrict__ out)
{
    __shared__ float sA[16][129];
    __shared__ float sB[16][129];
    __shared__ float sw[128];
    int tid = threadIdx.x;
    int j0 = blockIdx.x * 16, i0 = blockIdx.y * 16;

    for (int idx = tid; idx < 16 * 128; idx += 256) {
        int r = idx >> 7, k = idx & 127;
        sA[r][k] = hA[(i0 + r) * MLPD + k];
        sB[r][k] = hB[(j0 + r) * MLPD + k];
    }
    if (tid < 128) sw[tid] = W2[tid];
    __syncthreads();

    int tx = tid & 15, ty = tid >> 4;
    float acc = b2[0];
#pragma unroll 4
    for (int k = 0; k < 128; k++) {
        float v = sA[ty][k] + sB[tx][k];
        acc = fmaf(sw[k], tanhf_fast(v), acc);
    }
    int i = i0 + ty, j = j0 + tx;
    out[i * S_LEN + j] = (i == j) ? 0.f : acc;
}

// ---------------- launch ----------------
extern "C" void kernel_launch(void* const* d_in, const int* in_sizes, int n_in,
                              void* d_out, int out_size)
{
    int base = (in_sizes[2] < 1000) ? 3 : 2;

    const int* widx = (const int*)d_in[0];
    const int* pidx = (const int*)d_in[1];
    const float* W_word = (const float*)d_in[base + 0];
    const float* W_pos  = (const float*)d_in[base + 1];
    const float *Wih[4], *Whh[4], *bih[4], *bhh[4];
    for (int i = 0; i < 4; i++) {
        Wih[i] = (const float*)d_in[base + 2 + 4 * i];
        Whh[i] = (const float*)d_in[base + 3 + 4 * i];
        bih[i] = (const float*)d_in[base + 4 + 4 * i];
        bhh[i] = (const float*)d_in[base + 5 + 4 * i];
    }
    const float* W1 = (const float*)d_in[base + 18];
    const float* b1 = (const float*)d_in[base + 19];
    const float* W2 = (const float*)d_in[base + 20];
    const float* b2 = (const float*)d_in[base + 21];
    float* out = (float*)d_out;

    float *xp, *gxF, *gxB, *h0, *h1, *hA, *hB;
    cudaGetSymbolAddress((void**)&xp,  d_x);
    cudaGetSymbolAddress((void**)&gxF, d_gxF);
    cudaGetSymbolAddress((void**)&gxB, d_gxB);
    cudaGetSymbolAddress((void**)&h0,  d_h0);
    cudaGetSymbolAddress((void**)&h1,  d_h1);
    cudaGetSymbolAddress((void**)&hA,  d_hA);
    cudaGetSymbolAddress((void**)&hB,  d_hB);

    // 1) embeddings
    embed_kernel<<<S_LEN, EMB>>>(widx, pidx, W_word, W_pos);

    // 2) layer-0 input GEMMs: gx = x @ Wih^T + bih + bhh   [768,1024]
    dim3 gGX(G4 / 64, S_LEN / 64);
    gemm_bias_kernel<<<gGX, 256>>>(xp, EMB, Wih[0], EMB, bih[0], bhh[0], gxF, G4, S_LEN, G4, EMB);
    gemm_bias_kernel<<<gGX, 256>>>(xp, EMB, Wih[1], EMB, bih[1], bhh[1], gxB, G4, S_LEN, G4, EMB);

    // 3) layer-0 recurrence (fwd + bwd concurrently)
    lstm_kernel<<<16, 256>>>(Whh[0], Whh[1], gxF, gxB, h0);

    // 4) layer-1 input GEMMs: gx = h0 @ Wih^T + biases  (K = 512)
    gemm_bias_kernel<<<gGX, 256>>>(h0, 512, Wih[2], 512, bih[2], bhh[2], gxF, G4, S_LEN, G4, 512);
    gemm_bias_kernel<<<gGX, 256>>>(h0, 512, Wih[3], 512, bih[3], bhh[3], gxB, G4, S_LEN, G4, 512);

    // 5) layer-1 recurrence
    lstm_kernel<<<16, 256>>>(Whh[2], Whh[3], gxF, gxB, h1);

    // 6) scorer projections
    dim3 gAB(MLPD / 64, S_LEN / 64);
    gemm_bias_kernel<<<gAB, 256>>>(h1, 512, W1,       1024, b1,      nullptr, hA, MLPD, S_LEN, MLPD, 512);
    gemm_bias_kernel<<<gAB, 256>>>(h1, 512, W1 + 512, 1024, nullptr, nullptr, hB, MLPD, S_LEN, MLPD, 512);

    // 7) pairwise scores [768,768], diag = 0
    scorer_kernel<<<dim3(S_LEN / 16, S_LEN / 16), 256>>>(hA, hB, W2, b2, out);
}

// round 5
// speedup vs baseline: 2.1724x; 1.0149x over previous
#include <cuda_runtime.h>
#include <cstdint>
#include <math.h>

#define S_LEN 768
#define EMB   128
#define HDIM  256
#define G4    1024
#define MLPD  128

// ---------------- scratch (static device memory; no allocation) ----------------
__device__ float d_x  [S_LEN * EMB];
__device__ float d_gxF[S_LEN * G4];
__device__ float d_gxB[S_LEN * G4];
__device__ float d_h0 [S_LEN * 2 * HDIM];
__device__ float d_h1 [S_LEN * 2 * HDIM];
__device__ float d_hA [S_LEN * MLPD];
__device__ float d_hB [S_LEN * MLPD];

// ---------------- fast activations ----------------
__device__ __forceinline__ float sigmoidf_fast(float x) {
    return __fdividef(1.f, 1.f + __expf(-x));
}
__device__ __forceinline__ float tanhf_fast(float x) {
    float e = __expf(-2.f * fabsf(x));
    float r = __fdividef(1.f - e, 1.f + e);
    return copysignf(r, x);
}

// ---------------- cluster / mbarrier helpers ----------------
__device__ __forceinline__ uint32_t smem_u32(const void* p) {
    uint32_t a;
    asm("{ .reg .u64 t; cvta.to.shared.u64 t, %1; cvt.u32.u64 %0, t; }"
        : "=r"(a) : "l"(p));
    return a;
}
__device__ __forceinline__ uint32_t mapa_u32(uint32_t local_addr, uint32_t rank) {
    uint32_t rem;
    asm volatile("mapa.shared::cluster.u32 %0, %1, %2;"
                 : "=r"(rem) : "r"(local_addr), "r"(rank));
    return rem;
}
// async-proxy scalar store to a peer CTA's smem with tx accounting at that
// peer's mbarrier. Register-sourced: needs NO proxy fence, NO cluster fence.
__device__ __forceinline__ void st_async_b64(uint32_t rem_addr, unsigned long long v,
                                             uint32_t rem_bar) {
    asm volatile(
        "st.async.weak.shared::cluster.mbarrier::complete_tx::bytes.b64 [%0], %1, [%2];"
        :: "r"(rem_addr), "l"(v), "r"(rem_bar) : "memory");
}
__device__ __forceinline__ void arrive_expect_tx(uint32_t bar, uint32_t bytes) {
    asm volatile("mbarrier.arrive.expect_tx.shared.b64 _, [%0], %1;"
                 :: "r"(bar), "r"(bytes) : "memory");
}
// two-phase wait: fast try, then sleep-loop with timeout hint
__device__ __forceinline__ void wait_parity(uint32_t bar, uint32_t parity) {
    uint32_t done;
    asm volatile(
        "{\n\t"
        ".reg .pred P;\n\t"
        "mbarrier.try_wait.parity.acquire.cta.shared::cta.b64 P, [%1], %2;\n\t"
        "selp.b32 %0, 1, 0, P;\n\t"
        "}"
        : "=r"(done) : "r"(bar), "r"(parity) : "memory");
    if (!done) {
        asm volatile(
            "{\n\t"
            ".reg .pred P;\n\t"
            "W%=:\n\t"
            "mbarrier.try_wait.parity.acquire.cta.shared::cta.b64 P, [%0], %1, 0x989680;\n\t"
            "@!P bra W%=;\n\t"
            "}"
            :: "r"(bar), "r"(parity) : "memory");
    }
}
__device__ __forceinline__ void cluster_sync_() {
    asm volatile("barrier.cluster.arrive.aligned;" ::: "memory");
    asm volatile("barrier.cluster.wait.aligned;" ::: "memory");
}
__device__ __forceinline__ uint32_t cluster_rank_() {
    uint32_t r; asm("mov.u32 %0, %%cluster_ctarank;" : "=r"(r)); return r;
}

#define FMA2(acc, w, h) \
    asm("fma.rn.f32x2 %0, %1, %2, %0;" : "+l"(acc) : "l"(w), "l"(h))

// ---------------- embedding gather ----------------
__global__ void embed_kernel(const int* __restrict__ widx, const int* __restrict__ pidx,
                             const float* __restrict__ Ww, const float* __restrict__ Wp) {
    int s = blockIdx.x, f = threadIdx.x;
    float v = (f < 100) ? Ww[widx[s] * 100 + f] : Wp[pidx[s] * 28 + (f - 100)];
    d_x[s * EMB + f] = v;
}

// ---------------- generic C[M,N] = A[M,K] * B[N,K]^T + bias1 + bias2 ----------------
__global__ __launch_bounds__(256) void gemm_bias_kernel(
    const float* __restrict__ A, int lda,
    const float* __restrict__ B, int ldb,
    const float* __restrict__ bias1, const float* __restrict__ bias2,
    float* __restrict__ C, int ldc,
    int M, int N, int K)
{
    __shared__ __align__(16) float As[16][68];
    __shared__ __align__(16) float Bs[16][68];
    int tid = threadIdx.x;
    int bx = blockIdx.x, by = blockIdx.y;
    int tx = tid & 15, ty = tid >> 4;
    int m0 = by * 64 + ty * 4;
    int n0 = bx * 64 + tx * 4;
    float acc[4][4] = {};

    for (int k0 = 0; k0 < K; k0 += 16) {
#pragma unroll
        for (int i = 0; i < 4; i++) {
            int idx = tid + i * 256;
            int r = idx >> 4, kk = idx & 15;
            int col = k0 + kk;
            int mrow = by * 64 + r;
            int nrow = bx * 64 + r;
            As[kk][r] = (mrow < M && col < K) ? A[mrow * lda + col] : 0.f;
            Bs[kk][r] = (nrow < N && col < K) ? B[nrow * ldb + col] : 0.f;
        }
        __syncthreads();
#pragma unroll
        for (int kk = 0; kk < 16; kk++) {
            float4 av = *reinterpret_cast<const float4*>(&As[kk][ty * 4]);
            float4 bv = *reinterpret_cast<const float4*>(&Bs[kk][tx * 4]);
            float a[4] = {av.x, av.y, av.z, av.w};
            float b[4] = {bv.x, bv.y, bv.z, bv.w};
#pragma unroll
            for (int i = 0; i < 4; i++)
#pragma unroll
                for (int j = 0; j < 4; j++)
                    acc[i][j] = fmaf(a[i], b[j], acc[i][j]);
        }
        __syncthreads();
    }
#pragma unroll
    for (int i = 0; i < 4; i++)
#pragma unroll
        for (int j = 0; j < 4; j++) {
            int r = m0 + i, c = n0 + j;
            if (r < M && c < N) {
                float bv = 0.f;
                if (bias1) bv += bias1[c];
                if (bias2) bv += bias2[c];
                C[r * ldc + c] = acc[i][j] + bv;
            }
        }
}

// ---------------- BiLSTM recurrence: 2 clusters x 8 CTAs x 256 threads ----------------
// Warp-autonomous pipeline: warp w owns units 4w..4w+3. Lane layout within a
// warp: gate = lane>>3 (i,f,g,o), unit = (lane>>1)&3, half = lane&1. All four
// gates of a unit live in one warp, so after the dot product one shfl_xor
// reduce + three idx-shuffles deliver i/f/g/o — NO intra-CTA barrier, NO
// warp0 serialization. Each warp sends its 16B h-chunk to all 8 peers via
// st.async (register-sourced, async proxy, tx-accounted at the peer's
// ping-pong mbarrier) the moment it is done. expect_tx re-arm as in R4.
// Buffer anti-dependency: event-(t+1) writes into hbuf[t&1] require peers to
// pass wait(t), which requires THIS warp's event-t send, which happens after
// it read hbuf[t&1]. Warp skew is bounded because each event's single arrival
// comes from tid0's re-arm.
__global__ void __cluster_dims__(8, 1, 1) __launch_bounds__(256, 1)
lstm_kernel(const float* __restrict__ WhhF, const float* __restrict__ WhhB,
            const float* __restrict__ gxF,  const float* __restrict__ gxB,
            float* __restrict__ hout)
{
    __shared__ __align__(16) float hbuf[2][256];          // ping-pong full h vector
    __shared__ __align__(8) unsigned long long mbar[2];   // ping-pong (bar[t&1])

    int tid   = threadIdx.x;
    uint32_t crank = cluster_rank_();
    int dir   = blockIdx.x >> 3;           // 0 = fwd, 1 = bwd
    const float* Whh = dir ? WhhB : WhhF;
    const float* gx  = dir ? gxB  : gxF;

    int lane = tid & 31, w = tid >> 5;
    int gate = lane >> 3;                  // 0=i 1=f 2=g 3=o
    int ul   = (lane >> 1) & 3;            // unit within warp
    int hf   = lane & 1;                   // which half of h
    int unit = w * 4 + ul;                 // unit within CTA (0..31)
    int grow = gate * 256 + (int)crank * 32 + unit;

    // register-resident weights, packed f32x2 (128 floats per lane)
    unsigned long long w2[64];
    const ulonglong2* wsrc = reinterpret_cast<const ulonglong2*>(Whh + grow * 256 + hf * 128);
#pragma unroll
    for (int k = 0; k < 32; k++) {
        ulonglong2 v = wsrc[k];
        w2[2 * k] = v.x; w2[2 * k + 1] = v.y;
    }

    for (int i = tid; i < 512; i += 256) (&hbuf[0][0])[i] = 0.f;
    if (tid == 0) {
        uint32_t b0 = smem_u32(&mbar[0]);
        asm volatile("mbarrier.init.shared.b64 [%0], 1;" :: "r"(b0) : "memory");
        asm volatile("mbarrier.init.shared.b64 [%0], 1;" :: "r"(b0 + 8) : "memory");
    }
    __syncthreads();
    cluster_sync_();   // bars initialized + h zeroed before anyone sends

    uint32_t hbase   = smem_u32(&hbuf[0][0]);
    uint32_t barbase = smem_u32(&mbar[0]);

    // precomputed remote addresses (sender lanes 0..7; peer = lane)
    uint32_t mychunk = (uint32_t)crank * 128u + (uint32_t)w * 16u;
    uint32_t peer = (uint32_t)(lane & 7);
    uint32_t dstP0 = mapa_u32(hbase + mychunk,         peer);  // into hbuf[0]
    uint32_t dstP1 = mapa_u32(hbase + 1024u + mychunk, peer);  // into hbuf[1]
    uint32_t rb0   = mapa_u32(barbase,      peer);             // bar[0]
    uint32_t rb1   = mapa_u32(barbase + 8u, peer);             // bar[1]

    float cstate = 0.f;

    // prefetch first gx
    int s0 = dir ? (S_LEN - 1) : 0;
    float gxv = gx[s0 * G4 + grow];

    for (int t = 0; t < S_LEN; t++) {
        int s = dir ? (S_LEN - 1 - t) : t;

        // re-arm local bar for event t (this step's incoming deliveries)
        if (tid == 0)
            arrive_expect_tx(barbase + ((uint32_t)t & 1u) * 8u, 1024u);

        // wait for event t-1 (h(t) fully delivered into hbuf[t&1])
        if (t > 0) {
            uint32_t e = (uint32_t)(t - 1);
            wait_parity(barbase + (e & 1u) * 8u, (e >> 1) & 1u);
        }

        // prefetch next step's gx while we compute
        float gxn = 0.f;
        if (t + 1 < S_LEN) {
            int sn = dir ? (S_LEN - 2 - t) : (t + 1);
            gxn = gx[sn * G4 + grow];
        }

        // 128-wide dot product, packed f32x2, 4 accumulator chains
        const ulonglong2* hv = reinterpret_cast<const ulonglong2*>(&hbuf[t & 1][hf * 128]);
        unsigned long long a0 = 0ull, a1 = 0ull, a2 = 0ull, a3 = 0ull;
#pragma unroll
        for (int k = 0; k < 32; k += 2) {
            ulonglong2 hA2 = hv[k];
            ulonglong2 hB2 = hv[k + 1];
            FMA2(a0, w2[2 * k],     hA2.x);
            FMA2(a1, w2[2 * k + 1], hA2.y);
            FMA2(a2, w2[2 * k + 2], hB2.x);
            FMA2(a3, w2[2 * k + 3], hB2.y);
        }
        float f0, f1, f2, f3, f4, f5, f6, f7;
        asm("mov.b64 {%0, %1}, %2;" : "=f"(f0), "=f"(f1) : "l"(a0));
        asm("mov.b64 {%0, %1}, %2;" : "=f"(f2), "=f"(f3) : "l"(a1));
        asm("mov.b64 {%0, %1}, %2;" : "=f"(f4), "=f"(f5) : "l"(a2));
        asm("mov.b64 {%0, %1}, %2;" : "=f"(f6), "=f"(f7) : "l"(a3));
        float dot = ((f0 + f1) + (f2 + f3)) + ((f4 + f5) + (f6 + f7));
        dot += __shfl_xor_sync(0xffffffffu, dot, 1);   // both halves now hold full dot

        // gate pre-activation and unified activation (tanh(v) = 2*sigmoid(2v)-1)
        float v = gxv + dot;
        float z   = (gate == 2) ? 2.f * v : v;
        float sg  = sigmoidf_fast(z);
        float act = (gate == 2) ? fmaf(2.f, sg, -1.f) : sg;

        // gather f, g, o activations to the i-gate lanes of each unit
        int srcb = lane & 7;
        float gf = __shfl_sync(0xffffffffu, act, srcb + 8);
        float gg = __shfl_sync(0xffffffffu, act, srcb + 16);
        float go = __shfl_sync(0xffffffffu, act, srcb + 24);

        // cell update (meaningful only on unit lanes: gate==0 && hf==0; other
        // lanes compute garbage that is never read)
        cstate = fmaf(gf, cstate, act * gg);
        float hn = go * tanhf_fast(cstate);

        if (gate == 0 && hf == 0)
            hout[s * 512 + dir * 256 + (int)crank * 32 + unit] = hn;

        // broadcast the warp's 4 h values, then lanes 0..7 send 16B to peer=lane
        float h0 = __shfl_sync(0xffffffffu, hn, 0);
        float h1 = __shfl_sync(0xffffffffu, hn, 2);
        float h2 = __shfl_sync(0xffffffffu, hn, 4);
        float h3 = __shfl_sync(0xffffffffu, hn, 6);
        if (lane < 8) {
            unsigned long long p0, p1;
            asm("mov.b64 %0, {%1, %2};" : "=l"(p0) : "f"(h0), "f"(h1));
            asm("mov.b64 %0, {%1, %2};" : "=l"(p1) : "f"(h2), "f"(h3));
            uint32_t d = (t & 1) ? dstP0 : dstP1;   // write hbuf[(t+1)&1]
            uint32_t b = (t & 1) ? rb1   : rb0;     // account at bar[t&1]
            st_async_b64(d,      p0, b);
            st_async_b64(d + 8u, p1, b);
        }
        gxv = gxn;
    }

    // drain final event so no st.async is in flight when smem is torn down
    {
        uint32_t e = (uint32_t)(S_LEN - 1);
        wait_parity(barbase + (e & 1u) * 8u, (e >> 1) & 1u);
    }
    cluster_sync_();
}

// ---------------- pairwise scorer ----------------
__global__ __launch_bounds__(256) void scorer_kernel(
    const float* __restrict__ hA, const float* __restrict__ hB,
    const float* __restrict__ W2, const float* __restrict__ b2,
    float* __restrict__ out)
{
    __shared__ float sA[16][129];
    __shared__ float sB[16][129];
    __shared__ float sw[128];
    int tid = threadIdx.x;
    int j0 = blockIdx.x * 16, i0 = blockIdx.y * 16;

    for (int idx = tid; idx < 16 * 128; idx += 256) {
        int r = idx >> 7, k = idx & 127;
        sA[r][k] = hA[(i0 + r) * MLPD + k];
        sB[r][k] = hB[(j0 + r) * MLPD + k];
    }
    if (tid < 128) sw[tid] = W2[tid];
    __syncthreads();

    int tx = tid & 15, ty = tid >> 4;
    float acc = b2[0];
#pragma unroll 4
    for (int k = 0; k < 128; k++) {
        float v = sA[ty][k] + sB[tx][k];
        acc = fmaf(sw[k], tanhf_fast(v), acc);
    }
    int i = i0 + ty, j = j0 + tx;
    out[i * S_LEN + j] = (i == j) ? 0.f : acc;
}

// ---------------- launch ----------------
extern "C" void kernel_launch(void* const* d_in, const int* in_sizes, int n_in,
                              void* d_out, int out_size)
{
    int base = (in_sizes[2] < 1000) ? 3 : 2;

    const int* widx = (const int*)d_in[0];
    const int* pidx = (const int*)d_in[1];
    const float* W_word = (const float*)d_in[base + 0];
    const float* W_pos  = (const float*)d_in[base + 1];
    const float *Wih[4], *Whh[4], *bih[4], *bhh[4];
    for (int i = 0; i < 4; i++) {
        Wih[i] = (const float*)d_in[base + 2 + 4 * i];
        Whh[i] = (const float*)d_in[base + 3 + 4 * i];
        bih[i] = (const float*)d_in[base + 4 + 4 * i];
        bhh[i] = (const float*)d_in[base + 5 + 4 * i];
    }
    const float* W1 = (const float*)d_in[base + 18];
    const float* b1 = (const float*)d_in[base + 19];
    const float* W2 = (const float*)d_in[base + 20];
    const float* b2 = (const float*)d_in[base + 21];
    float* out = (float*)d_out;

    float *xp, *gxF, *gxB, *h0, *h1, *hA, *hB;
    cudaGetSymbolAddress((void**)&xp,  d_x);
    cudaGetSymbolAddress((void**)&gxF, d_gxF);
    cudaGetSymbolAddress((void**)&gxB, d_gxB);
    cudaGetSymbolAddress((void**)&h0,  d_h0);
    cudaGetSymbolAddress((void**)&h1,  d_h1);
    cudaGetSymbolAddress((void**)&hA,  d_hA);
    cudaGetSymbolAddress((void**)&hB,  d_hB);

    // 1) embeddings
    embed_kernel<<<S_LEN, EMB>>>(widx, pidx, W_word, W_pos);

    // 2) layer-0 input GEMMs: gx = x @ Wih^T + bih + bhh   [768,1024]
    dim3 gGX(G4 / 64, S_LEN / 64);
    gemm_bias_kernel<<<gGX, 256>>>(xp, EMB, Wih[0], EMB, bih[0], bhh[0], gxF, G4, S_LEN, G4, EMB);
    gemm_bias_kernel<<<gGX, 256>>>(xp, EMB, Wih[1], EMB, bih[1], bhh[1], gxB, G4, S_LEN, G4, EMB);

    // 3) layer-0 recurrence (fwd + bwd concurrently)
    lstm_kernel<<<16, 256>>>(Whh[0], Whh[1], gxF, gxB, h0);

    // 4) layer-1 input GEMMs: gx = h0 @ Wih^T + biases  (K = 512)
    gemm_bias_kernel<<<gGX, 256>>>(h0, 512, Wih[2], 512, bih[2], bhh[2], gxF, G4, S_LEN, G4, 512);
    gemm_bias_kernel<<<gGX, 256>>>(h0, 512, Wih[3], 512, bih[3], bhh[3], gxB, G4, S_LEN, G4, 512);

    // 5) layer-1 recurrence
    lstm_kernel<<<16, 256>>>(Whh[2], Whh[3], gxF, gxB, h1);

    // 6) scorer projections
    dim3 gAB(MLPD / 64, S_LEN / 64);
    gemm_bias_kernel<<<gAB, 256>>>(h1, 512, W1,       1024, b1,      nullptr, hA, MLPD, S_LEN, MLPD, 512);
    gemm_bias_kernel<<<gAB, 256>>>(h1, 512, W1 + 512, 1024, nullptr, nullptr, hB, MLPD, S_LEN, MLPD, 512);

    // 7) pairwise scores [768,768], diag = 0
    scorer_kernel<<<dim3(S_LEN / 16, S_LEN / 16), 256>>>(hA, hB, W2, b2, out);
}